// round 2
// baseline (speedup 1.0000x reference)
#include <cuda_runtime.h>
#include <math_constants.h>

#define N_NODES 1000000
#define N_EDGES 32000000
#define H 20
#define NREG 21   // H thresholds -> up to H+1 regions
#define ABPAD 21  // shared-memory row stride (odd -> conflict-light)

// Scratch (no cudaMalloc allowed)
__device__ float  g_agg[N_NODES];
__device__ float  g_s[H];            // sorted layer-1 thresholds (+INF pads)
__device__ float2 g_AB[NREG * H];    // per-region affine map of layer-2 preacts

// ---------------------------------------------------------------------------
// 1) agg[i] = (1 + eps) * x[i]   (self term folded into the accumulator)
// ---------------------------------------------------------------------------
__global__ void init_kernel(const float* __restrict__ x,
                            const float* __restrict__ eps) {
    int i = blockIdx.x * blockDim.x + threadIdx.x;
    if (i < N_NODES) {
        float e = 1.0f + __ldg(eps);
        g_agg[i] = e * x[i];
    }
}

// ---------------------------------------------------------------------------
// 2) scatter-add: agg[dst] += x[src].
//    edge_index is int32 (JAX default config downcasts int64 -> int32).
//    int4 loads: 4 edges per 16B index load, x + agg are L2-resident (8 MB).
// ---------------------------------------------------------------------------
__global__ void edge_kernel(const int* __restrict__ ei,
                            const float* __restrict__ x) {
    const int4* src4 = (const int4*)(ei);
    const int4* dst4 = (const int4*)(ei + N_EDGES);
    int t  = blockIdx.x * blockDim.x + threadIdx.x;
    int nt = gridDim.x * blockDim.x;
    const int total4 = N_EDGES / 4;
    for (int j = t; j < total4; j += nt) {
        int4 s = src4[j];
        int4 d = dst4[j];
        float v0 = __ldg(&x[s.x]);
        float v1 = __ldg(&x[s.y]);
        float v2 = __ldg(&x[s.z]);
        float v3 = __ldg(&x[s.w]);
        atomicAdd(&g_agg[d.x], v0);
        atomicAdd(&g_agg[d.y], v1);
        atomicAdd(&g_agg[d.z], v2);
        atomicAdd(&g_agg[d.w], v3);
    }
}

// ---------------------------------------------------------------------------
// 3) Collapse layers 1+2 per region of scalar h.
//    Region r = #{sorted thresholds < h}. Unit k active in region r:
//      w1_k > 0 : pos_k <  r
//      w1_k < 0 : pos_k >= r
//      w1_k = 0 : b1_k > 0 (constant)
//    u_j(h) = A[r][j]*h + B[r][j],  A = sum_k m*w1_k*w2_kj,
//                                    B = b2_j + sum_k m*b1_k*w2_kj
// ---------------------------------------------------------------------------
__global__ void precompute_kernel(const float* __restrict__ w1,
                                  const float* __restrict__ b1,
                                  const float* __restrict__ w2,
                                  const float* __restrict__ b2) {
    __shared__ float t[H];
    __shared__ int   cls[H];   // 0: w1>0, 1: w1<0, 2: w1==0 always-on, 3: always-off
    __shared__ int   pos[H];
    __shared__ float sw1[H], sb1[H];
    __shared__ float ssort[H];
    int tid = threadIdx.x;

    if (tid < H) {
        float w = w1[tid], b = b1[tid];
        sw1[tid] = w; sb1[tid] = b;
        if (w > 0.0f)      { cls[tid] = 0; t[tid] = -b / w; }
        else if (w < 0.0f) { cls[tid] = 1; t[tid] = -b / w; }
        else               { cls[tid] = (b > 0.0f) ? 2 : 3; t[tid] = 0.0f; }
        ssort[tid] = CUDART_INF_F;
    }
    __syncthreads();

    if (tid < H && cls[tid] < 2) {
        float tk = t[tid];
        int p = 0;
        for (int m = 0; m < H; m++) {
            if (cls[m] < 2) {
                float tm = t[m];
                if (tm < tk || (tm == tk && m < tid)) p++;
            }
        }
        pos[tid]  = p;
        ssort[p]  = tk;
    }
    __syncthreads();

    if (tid < H) g_s[tid] = ssort[tid];

    if (tid < NREG * H) {
        int r = tid / H, j = tid % H;
        float A = 0.0f;
        float B = __ldg(&b2[j]);
        for (int k = 0; k < H; k++) {
            int c = cls[k];
            bool m;
            if (c == 0)      m = (pos[k] <  r);
            else if (c == 1) m = (pos[k] >= r);
            else             m = (c == 2);
            if (m) {
                float wkj = __ldg(&w2[k * H + j]);
                A = fmaf(sw1[k], wkj, A);
                B = fmaf(sb1[k], wkj, B);
            }
        }
        g_AB[r * H + j] = make_float2(A, B);
    }
}

// ---------------------------------------------------------------------------
// 4) Per node: region lookup + collapsed MLP (40 FMA instead of 420)
// ---------------------------------------------------------------------------
__global__ void node_kernel(float* __restrict__ out,
                            const float* __restrict__ w3,
                            const float* __restrict__ b3) {
    __shared__ float2 sAB[NREG * ABPAD];
    for (int i = threadIdx.x; i < NREG * H; i += blockDim.x) {
        int r = i / H, j = i % H;
        sAB[r * ABPAD + j] = g_AB[i];
    }
    float sreg[H], w3r[H];
    #pragma unroll
    for (int m = 0; m < H; m++) {
        sreg[m] = g_s[m];
        w3r[m]  = __ldg(&w3[m]);
    }
    float bias3 = __ldg(&b3[0]);
    __syncthreads();

    int t  = blockIdx.x * blockDim.x + threadIdx.x;
    int nt = gridDim.x * blockDim.x;
    for (int i = t; i < N_NODES; i += nt) {
        float h = g_agg[i];
        int r = 0;
        #pragma unroll
        for (int m = 0; m < H; m++) r += (sreg[m] < h) ? 1 : 0;
        const float2* row = &sAB[r * ABPAD];
        float acc = bias3;
        #pragma unroll
        for (int j = 0; j < H; j++) {
            float2 ab = row[j];
            float u = fmaf(ab.x, h, ab.y);
            acc = fmaf(fmaxf(u, 0.0f), w3r[j], acc);
        }
        out[i] = acc;
    }
}

// ---------------------------------------------------------------------------
extern "C" void kernel_launch(void* const* d_in, const int* in_sizes, int n_in,
                              void* d_out, int out_size) {
    const float* x   = (const float*)d_in[0];
    const int*   ei  = (const int*)d_in[1];
    const float* eps = (const float*)d_in[2];
    const float* w1  = (const float*)d_in[3];
    const float* b1  = (const float*)d_in[4];
    const float* w2  = (const float*)d_in[5];
    const float* b2  = (const float*)d_in[6];
    const float* w3  = (const float*)d_in[7];
    const float* b3  = (const float*)d_in[8];
    float* out = (float*)d_out;

    init_kernel<<<(N_NODES + 255) / 256, 256>>>(x, eps);
    edge_kernel<<<1184, 256>>>(ei, x);
    precompute_kernel<<<1, 448>>>(w1, b1, w2, b2);
    node_kernel<<<512, 256>>>(out, w3, b3);
}

// round 3
// speedup vs baseline: 1.0790x; 1.0790x over previous
#include <cuda_runtime.h>
#include <math_constants.h>

#define N_NODES 1000000
#define N_EDGES 32000000
#define H 20
#define NREG 21   // H thresholds -> up to H+1 regions
#define ABPAD 21  // shared-memory row stride (odd -> conflict-light)

// Scratch (no cudaMalloc allowed)
__device__ float  g_agg[N_NODES];
__device__ float  g_s[H];            // sorted layer-1 thresholds (+INF pads)
__device__ float2 g_AB[NREG * H];    // per-region affine map of layer-2 preacts

// ---------------------------------------------------------------------------
// 1) agg[i] = (1 + eps) * x[i]   (self term folded into the accumulator;
//    also warms x and g_agg into L2 ahead of the edge kernel)
// ---------------------------------------------------------------------------
__global__ void init_kernel(const float* __restrict__ x,
                            const float* __restrict__ eps) {
    int i = blockIdx.x * blockDim.x + threadIdx.x;
    if (i < N_NODES) {
        float e = 1.0f + __ldg(eps);
        g_agg[i] = e * x[i];
    }
}

// ---------------------------------------------------------------------------
// 2) scatter-add: agg[dst] += x[src].
//    Flat (no grid-stride loop): 8 edges per thread, all index loads issued
//    up front (2x int4 src + 2x int4 dst), then 8 independent L2 gathers,
//    then 8 REDs. Latency hidden by 26 waves of TLP instead of per-thread
//    software pipelining.
// ---------------------------------------------------------------------------
#define EDGES_PER_THREAD 8
__global__ void edge_kernel(const int* __restrict__ ei,
                            const float* __restrict__ x) {
    const int4* src4 = (const int4*)(ei);
    const int4* dst4 = (const int4*)(ei + N_EDGES);
    int t = blockIdx.x * blockDim.x + threadIdx.x;   // one batch of 8 edges
    int j = t * 2;                                    // int4 index
    // N_EDGES / 8 = 4,000,000 threads exactly; grid sized to match.
    int4 s0 = src4[j];
    int4 s1 = src4[j + 1];
    int4 d0 = dst4[j];
    int4 d1 = dst4[j + 1];
    float v0 = __ldg(&x[s0.x]);
    float v1 = __ldg(&x[s0.y]);
    float v2 = __ldg(&x[s0.z]);
    float v3 = __ldg(&x[s0.w]);
    float v4 = __ldg(&x[s1.x]);
    float v5 = __ldg(&x[s1.y]);
    float v6 = __ldg(&x[s1.z]);
    float v7 = __ldg(&x[s1.w]);
    atomicAdd(&g_agg[d0.x], v0);
    atomicAdd(&g_agg[d0.y], v1);
    atomicAdd(&g_agg[d0.z], v2);
    atomicAdd(&g_agg[d0.w], v3);
    atomicAdd(&g_agg[d1.x], v4);
    atomicAdd(&g_agg[d1.y], v5);
    atomicAdd(&g_agg[d1.z], v6);
    atomicAdd(&g_agg[d1.w], v7);
}

// ---------------------------------------------------------------------------
// 3) Collapse layers 1+2 per region of scalar h.
//    Region r = #{sorted thresholds < h}. Unit k active in region r:
//      w1_k > 0 : pos_k <  r
//      w1_k < 0 : pos_k >= r
//      w1_k = 0 : b1_k > 0 (constant)
//    u_j(h) = A[r][j]*h + B[r][j],  A = sum_k m*w1_k*w2_kj,
//                                    B = b2_j + sum_k m*b1_k*w2_kj
// ---------------------------------------------------------------------------
__global__ void precompute_kernel(const float* __restrict__ w1,
                                  const float* __restrict__ b1,
                                  const float* __restrict__ w2,
                                  const float* __restrict__ b2) {
    __shared__ float t[H];
    __shared__ int   cls[H];   // 0: w1>0, 1: w1<0, 2: w1==0 always-on, 3: always-off
    __shared__ int   pos[H];
    __shared__ float sw1[H], sb1[H];
    __shared__ float ssort[H];
    int tid = threadIdx.x;

    if (tid < H) {
        float w = w1[tid], b = b1[tid];
        sw1[tid] = w; sb1[tid] = b;
        if (w > 0.0f)      { cls[tid] = 0; t[tid] = -b / w; }
        else if (w < 0.0f) { cls[tid] = 1; t[tid] = -b / w; }
        else               { cls[tid] = (b > 0.0f) ? 2 : 3; t[tid] = 0.0f; }
        ssort[tid] = CUDART_INF_F;
    }
    __syncthreads();

    if (tid < H && cls[tid] < 2) {
        float tk = t[tid];
        int p = 0;
        for (int m = 0; m < H; m++) {
            if (cls[m] < 2) {
                float tm = t[m];
                if (tm < tk || (tm == tk && m < tid)) p++;
            }
        }
        pos[tid]  = p;
        ssort[p]  = tk;
    }
    __syncthreads();

    if (tid < H) g_s[tid] = ssort[tid];

    if (tid < NREG * H) {
        int r = tid / H, j = tid % H;
        float A = 0.0f;
        float B = __ldg(&b2[j]);
        for (int k = 0; k < H; k++) {
            int c = cls[k];
            bool m;
            if (c == 0)      m = (pos[k] <  r);
            else if (c == 1) m = (pos[k] >= r);
            else             m = (c == 2);
            if (m) {
                float wkj = __ldg(&w2[k * H + j]);
                A = fmaf(sw1[k], wkj, A);
                B = fmaf(sb1[k], wkj, B);
            }
        }
        g_AB[r * H + j] = make_float2(A, B);
    }
}

// ---------------------------------------------------------------------------
// 4) Per node: region lookup + collapsed MLP (40 FMA instead of 420)
// ---------------------------------------------------------------------------
__global__ void node_kernel(float* __restrict__ out,
                            const float* __restrict__ w3,
                            const float* __restrict__ b3) {
    __shared__ float2 sAB[NREG * ABPAD];
    for (int i = threadIdx.x; i < NREG * H; i += blockDim.x) {
        int r = i / H, j = i % H;
        sAB[r * ABPAD + j] = g_AB[i];
    }
    float sreg[H], w3r[H];
    #pragma unroll
    for (int m = 0; m < H; m++) {
        sreg[m] = g_s[m];
        w3r[m]  = __ldg(&w3[m]);
    }
    float bias3 = __ldg(&b3[0]);
    __syncthreads();

    int t  = blockIdx.x * blockDim.x + threadIdx.x;
    int nt = gridDim.x * blockDim.x;
    for (int i = t; i < N_NODES; i += nt) {
        float h = g_agg[i];
        int r = 0;
        #pragma unroll
        for (int m = 0; m < H; m++) r += (sreg[m] < h) ? 1 : 0;
        const float2* row = &sAB[r * ABPAD];
        float acc = bias3;
        #pragma unroll
        for (int j = 0; j < H; j++) {
            float2 ab = row[j];
            float u = fmaf(ab.x, h, ab.y);
            acc = fmaf(fmaxf(u, 0.0f), w3r[j], acc);
        }
        out[i] = acc;
    }
}

// ---------------------------------------------------------------------------
extern "C" void kernel_launch(void* const* d_in, const int* in_sizes, int n_in,
                              void* d_out, int out_size) {
    const float* x   = (const float*)d_in[0];
    const int*   ei  = (const int*)d_in[1];
    const float* eps = (const float*)d_in[2];
    const float* w1  = (const float*)d_in[3];
    const float* b1  = (const float*)d_in[4];
    const float* w2  = (const float*)d_in[5];
    const float* b2  = (const float*)d_in[6];
    const float* w3  = (const float*)d_in[7];
    const float* b3  = (const float*)d_in[8];
    float* out = (float*)d_out;

    init_kernel<<<(N_NODES + 255) / 256, 256>>>(x, eps);
    // 32M edges / 8 per thread = 4M threads = 15625 blocks of 256
    edge_kernel<<<(N_EDGES / EDGES_PER_THREAD + 255) / 256, 256>>>(ei, x);
    precompute_kernel<<<1, 448>>>(w1, b1, w2, b2);
    node_kernel<<<512, 256>>>(out, w3, b3);
}

// round 4
// speedup vs baseline: 1.1084x; 1.0273x over previous
#include <cuda_runtime.h>
#include <math_constants.h>

#define N_NODES 1000000
#define N_EDGES 32000000
#define H 20
#define NREG 21   // H thresholds -> up to H+1 regions
#define ABPAD 21  // shared-memory row stride (odd -> conflict-light)

// Scratch (no cudaMalloc allowed)
__device__ float  g_agg[N_NODES];
__device__ float  g_s[H];            // sorted layer-1 thresholds (+INF pads)
__device__ float2 g_AB[NREG * H];    // per-region affine map of layer-2 preacts

// ---------------------------------------------------------------------------
// 1) zero the accumulator (self term now folded into node_kernel).
//    float4 stores: 250K threads, pure STG traffic.
// ---------------------------------------------------------------------------
__global__ void zero_kernel() {
    int i = blockIdx.x * blockDim.x + threadIdx.x;
    if (i < N_NODES / 4) {
        ((float4*)g_agg)[i] = make_float4(0.f, 0.f, 0.f, 0.f);
    }
}

// ---------------------------------------------------------------------------
// 2) scatter-add: agg[dst] += x[src].
//    8 edges/thread flat. Index loads use __ldcs (evict-first streaming) so
//    the 256MB index stream does not evict the hot 8MB x/agg set from L2 —
//    the scattered gathers and REDs must stay L2-resident.
// ---------------------------------------------------------------------------
#define EDGES_PER_THREAD 8
__global__ void edge_kernel(const int* __restrict__ ei,
                            const float* __restrict__ x) {
    const int4* src4 = (const int4*)(ei);
    const int4* dst4 = (const int4*)(ei + N_EDGES);
    int t = blockIdx.x * blockDim.x + threadIdx.x;
    int j = t * 2;
    int4 s0 = __ldcs(&src4[j]);
    int4 s1 = __ldcs(&src4[j + 1]);
    int4 d0 = __ldcs(&dst4[j]);
    int4 d1 = __ldcs(&dst4[j + 1]);
    float v0 = __ldg(&x[s0.x]);
    float v1 = __ldg(&x[s0.y]);
    float v2 = __ldg(&x[s0.z]);
    float v3 = __ldg(&x[s0.w]);
    float v4 = __ldg(&x[s1.x]);
    float v5 = __ldg(&x[s1.y]);
    float v6 = __ldg(&x[s1.z]);
    float v7 = __ldg(&x[s1.w]);
    atomicAdd(&g_agg[d0.x], v0);
    atomicAdd(&g_agg[d0.y], v1);
    atomicAdd(&g_agg[d0.z], v2);
    atomicAdd(&g_agg[d0.w], v3);
    atomicAdd(&g_agg[d1.x], v4);
    atomicAdd(&g_agg[d1.y], v5);
    atomicAdd(&g_agg[d1.z], v6);
    atomicAdd(&g_agg[d1.w], v7);
}

// ---------------------------------------------------------------------------
// 3) Collapse layers 1+2 per region of scalar h (unchanged, exact regroup).
// ---------------------------------------------------------------------------
__global__ void precompute_kernel(const float* __restrict__ w1,
                                  const float* __restrict__ b1,
                                  const float* __restrict__ w2,
                                  const float* __restrict__ b2) {
    __shared__ float t[H];
    __shared__ int   cls[H];   // 0: w1>0, 1: w1<0, 2: w1==0 always-on, 3: always-off
    __shared__ int   pos[H];
    __shared__ float sw1[H], sb1[H];
    __shared__ float ssort[H];
    int tid = threadIdx.x;

    if (tid < H) {
        float w = w1[tid], b = b1[tid];
        sw1[tid] = w; sb1[tid] = b;
        if (w > 0.0f)      { cls[tid] = 0; t[tid] = -b / w; }
        else if (w < 0.0f) { cls[tid] = 1; t[tid] = -b / w; }
        else               { cls[tid] = (b > 0.0f) ? 2 : 3; t[tid] = 0.0f; }
        ssort[tid] = CUDART_INF_F;
    }
    __syncthreads();

    if (tid < H && cls[tid] < 2) {
        float tk = t[tid];
        int p = 0;
        for (int m = 0; m < H; m++) {
            if (cls[m] < 2) {
                float tm = t[m];
                if (tm < tk || (tm == tk && m < tid)) p++;
            }
        }
        pos[tid]  = p;
        ssort[p]  = tk;
    }
    __syncthreads();

    if (tid < H) g_s[tid] = ssort[tid];

    if (tid < NREG * H) {
        int r = tid / H, j = tid % H;
        float A = 0.0f;
        float B = __ldg(&b2[j]);
        for (int k = 0; k < H; k++) {
            int c = cls[k];
            bool m;
            if (c == 0)      m = (pos[k] <  r);
            else if (c == 1) m = (pos[k] >= r);
            else             m = (c == 2);
            if (m) {
                float wkj = __ldg(&w2[k * H + j]);
                A = fmaf(sw1[k], wkj, A);
                B = fmaf(sb1[k], wkj, B);
            }
        }
        g_AB[r * H + j] = make_float2(A, B);
    }
}

// ---------------------------------------------------------------------------
// 4) Per node (flat, 1 node/thread): h = (1+eps)*x + agg, then region lookup
//    + collapsed MLP (40 FMA instead of 420).
// ---------------------------------------------------------------------------
__global__ void node_kernel(float* __restrict__ out,
                            const float* __restrict__ x,
                            const float* __restrict__ eps,
                            const float* __restrict__ w3,
                            const float* __restrict__ b3) {
    __shared__ float2 sAB[NREG * ABPAD];
    for (int i = threadIdx.x; i < NREG * H; i += blockDim.x) {
        int r = i / H, j = i % H;
        sAB[r * ABPAD + j] = g_AB[i];
    }
    float sreg[H], w3r[H];
    #pragma unroll
    for (int m = 0; m < H; m++) {
        sreg[m] = g_s[m];
        w3r[m]  = __ldg(&w3[m]);
    }
    float bias3 = __ldg(&b3[0]);
    float e = 1.0f + __ldg(eps);
    __syncthreads();

    int i = blockIdx.x * blockDim.x + threadIdx.x;
    if (i < N_NODES) {
        float h = fmaf(e, x[i], g_agg[i]);
        int r = 0;
        #pragma unroll
        for (int m = 0; m < H; m++) r += (sreg[m] < h) ? 1 : 0;
        const float2* row = &sAB[r * ABPAD];
        float acc = bias3;
        #pragma unroll
        for (int j = 0; j < H; j++) {
            float2 ab = row[j];
            float u = fmaf(ab.x, h, ab.y);
            acc = fmaf(fmaxf(u, 0.0f), w3r[j], acc);
        }
        out[i] = acc;
    }
}

// ---------------------------------------------------------------------------
extern "C" void kernel_launch(void* const* d_in, const int* in_sizes, int n_in,
                              void* d_out, int out_size) {
    const float* x   = (const float*)d_in[0];
    const int*   ei  = (const int*)d_in[1];
    const float* eps = (const float*)d_in[2];
    const float* w1  = (const float*)d_in[3];
    const float* b1  = (const float*)d_in[4];
    const float* w2  = (const float*)d_in[5];
    const float* b2  = (const float*)d_in[6];
    const float* w3  = (const float*)d_in[7];
    const float* b3  = (const float*)d_in[8];
    float* out = (float*)d_out;

    zero_kernel<<<(N_NODES / 4 + 255) / 256, 256>>>();
    edge_kernel<<<(N_EDGES / EDGES_PER_THREAD + 255) / 256, 256>>>(ei, x);
    precompute_kernel<<<1, 448>>>(w1, b1, w2, b2);
    node_kernel<<<(N_NODES + 255) / 256, 256>>>(out, x, eps, w3, b3);
}

// round 5
// speedup vs baseline: 1.1185x; 1.0091x over previous
#include <cuda_runtime.h>
#include <math_constants.h>

#define N_NODES 1000000
#define N_EDGES 32000000
#define H 20
#define NREG 21   // H thresholds -> up to H+1 regions

// Scratch (no cudaMalloc allowed)
__device__ float  g_agg[N_NODES];
__device__ float  g_s[H];            // sorted layer-1 thresholds (+INF pads)
__device__ float2 g_AB[NREG * H];    // per-region affine map of layer-2 preacts

// ---------------------------------------------------------------------------
// 1) scatter-add: agg[dst] += x[src].
//    8 edges/thread flat; at the L1tex scattered-wavefront floor
//    (64M lane-ops: 32M gathers + 32M REDs), ~240us is the HW limit here.
// ---------------------------------------------------------------------------
#define EDGES_PER_THREAD 8
__global__ void edge_kernel(const int* __restrict__ ei,
                            const float* __restrict__ x) {
    const int4* src4 = (const int4*)(ei);
    const int4* dst4 = (const int4*)(ei + N_EDGES);
    int t = blockIdx.x * blockDim.x + threadIdx.x;
    int j = t * 2;
    int4 s0 = __ldcs(&src4[j]);
    int4 s1 = __ldcs(&src4[j + 1]);
    int4 d0 = __ldcs(&dst4[j]);
    int4 d1 = __ldcs(&dst4[j + 1]);
    float v0 = __ldg(&x[s0.x]);
    float v1 = __ldg(&x[s0.y]);
    float v2 = __ldg(&x[s0.z]);
    float v3 = __ldg(&x[s0.w]);
    float v4 = __ldg(&x[s1.x]);
    float v5 = __ldg(&x[s1.y]);
    float v6 = __ldg(&x[s1.z]);
    float v7 = __ldg(&x[s1.w]);
    atomicAdd(&g_agg[d0.x], v0);
    atomicAdd(&g_agg[d0.y], v1);
    atomicAdd(&g_agg[d0.z], v2);
    atomicAdd(&g_agg[d0.w], v3);
    atomicAdd(&g_agg[d1.x], v4);
    atomicAdd(&g_agg[d1.y], v5);
    atomicAdd(&g_agg[d1.z], v6);
    atomicAdd(&g_agg[d1.w], v7);
}

// ---------------------------------------------------------------------------
// 2) Collapse layers 1+2 per region of scalar h (exact regroup).
// ---------------------------------------------------------------------------
__global__ void precompute_kernel(const float* __restrict__ w1,
                                  const float* __restrict__ b1,
                                  const float* __restrict__ w2,
                                  const float* __restrict__ b2) {
    __shared__ float t[H];
    __shared__ int   cls[H];   // 0: w1>0, 1: w1<0, 2: w1==0 always-on, 3: always-off
    __shared__ int   pos[H];
    __shared__ float sw1[H], sb1[H];
    __shared__ float ssort[H];
    int tid = threadIdx.x;

    if (tid < H) {
        float w = w1[tid], b = b1[tid];
        sw1[tid] = w; sb1[tid] = b;
        if (w > 0.0f)      { cls[tid] = 0; t[tid] = -b / w; }
        else if (w < 0.0f) { cls[tid] = 1; t[tid] = -b / w; }
        else               { cls[tid] = (b > 0.0f) ? 2 : 3; t[tid] = 0.0f; }
        ssort[tid] = CUDART_INF_F;
    }
    __syncthreads();

    if (tid < H && cls[tid] < 2) {
        float tk = t[tid];
        int p = 0;
        for (int m = 0; m < H; m++) {
            if (cls[m] < 2) {
                float tm = t[m];
                if (tm < tk || (tm == tk && m < tid)) p++;
            }
        }
        pos[tid]  = p;
        ssort[p]  = tk;
    }
    __syncthreads();

    if (tid < H) g_s[tid] = ssort[tid];

    if (tid < NREG * H) {
        int r = tid / H, j = tid % H;
        float A = 0.0f;
        float B = __ldg(&b2[j]);
        for (int k = 0; k < H; k++) {
            int c = cls[k];
            bool m;
            if (c == 0)      m = (pos[k] <  r);
            else if (c == 1) m = (pos[k] >= r);
            else             m = (c == 2);
            if (m) {
                float wkj = __ldg(&w2[k * H + j]);
                A = fmaf(sw1[k], wkj, A);
                B = fmaf(sb1[k], wkj, B);
            }
        }
        g_AB[r * H + j] = make_float2(A, B);
    }
}

// ---------------------------------------------------------------------------
// 3) Per node: h = (1+eps)*x + agg, region lookup, collapsed MLP (40 FMA).
//    sAB transposed to [j][r]: lanes with different regions read within a
//    168B window per j -> shared-mem conflict degree <=2 (was ~8-21).
// ---------------------------------------------------------------------------
__global__ void node_kernel(float* __restrict__ out,
                            const float* __restrict__ x,
                            const float* __restrict__ eps,
                            const float* __restrict__ w3,
                            const float* __restrict__ b3) {
    __shared__ float2 sAB[H * NREG];   // [j][r]
    for (int i = threadIdx.x; i < NREG * H; i += blockDim.x) {
        int r = i / H, j = i % H;
        sAB[j * NREG + r] = g_AB[i];
    }
    float sreg[H], w3r[H];
    #pragma unroll
    for (int m = 0; m < H; m++) {
        sreg[m] = g_s[m];
        w3r[m]  = __ldg(&w3[m]);
    }
    float bias3 = __ldg(&b3[0]);
    float e = 1.0f + __ldg(eps);
    __syncthreads();

    int t  = blockIdx.x * blockDim.x + threadIdx.x;
    int nt = gridDim.x * blockDim.x;
    for (int i = t; i < N_NODES; i += nt) {
        float h = fmaf(e, x[i], g_agg[i]);
        int r = 0;
        #pragma unroll
        for (int m = 0; m < H; m++) r += (sreg[m] < h) ? 1 : 0;
        float acc = bias3;
        #pragma unroll
        for (int j = 0; j < H; j++) {
            float2 ab = sAB[j * NREG + r];
            float u = fmaf(ab.x, h, ab.y);
            acc = fmaf(fmaxf(u, 0.0f), w3r[j], acc);
        }
        out[i] = acc;
    }
}

// ---------------------------------------------------------------------------
extern "C" void kernel_launch(void* const* d_in, const int* in_sizes, int n_in,
                              void* d_out, int out_size) {
    const float* x   = (const float*)d_in[0];
    const int*   ei  = (const int*)d_in[1];
    const float* eps = (const float*)d_in[2];
    const float* w1  = (const float*)d_in[3];
    const float* b1  = (const float*)d_in[4];
    const float* w2  = (const float*)d_in[5];
    const float* b2  = (const float*)d_in[6];
    const float* w3  = (const float*)d_in[7];
    const float* b3  = (const float*)d_in[8];
    float* out = (float*)d_out;

    // zero the accumulator via memset node (no kernel launch, no alloc)
    void* agg_ptr = nullptr;
    cudaGetSymbolAddress(&agg_ptr, g_agg);
    cudaMemsetAsync(agg_ptr, 0, N_NODES * sizeof(float));

    edge_kernel<<<(N_EDGES / EDGES_PER_THREAD + 255) / 256, 256>>>(ei, x);
    precompute_kernel<<<1, 448>>>(w1, b1, w2, b2);
    node_kernel<<<512, 256>>>(out, x, eps, w3, b3);
}

// round 6
// speedup vs baseline: 1.1537x; 1.0315x over previous
#include <cuda_runtime.h>
#include <math_constants.h>

#define N_NODES 1000000
#define N_EDGES 32000000
#define H 20
#define NREG 21   // H thresholds -> up to H+1 regions

#define EDGES_PER_THREAD 8
#define EDGE_BLOCKS (N_EDGES / EDGES_PER_THREAD / 256)   // 15625

// Scratch (no cudaMalloc allowed). Zero-initialized at module load;
// node_kernel re-zeroes g_agg after consuming it so every graph replay
// starts from a clean accumulator (no memset launch needed).
__device__ float  g_agg[N_NODES];
__device__ float  g_s[H];            // sorted layer-1 thresholds (+INF pads)
__device__ float2 g_AB[NREG * H];    // per-region affine map of layer-2 preacts

// ---------------------------------------------------------------------------
// 1) Fused: edge blocks do scatter-add agg[dst] += x[src] (at the L1tex/L2
//    scattered-op floor, ~250us); one extra block collapses MLP layers 1+2
//    into per-region affine maps, fully hidden under the edge work.
// ---------------------------------------------------------------------------
__global__ void edge_precompute_kernel(const int* __restrict__ ei,
                                       const float* __restrict__ x,
                                       const float* __restrict__ w1,
                                       const float* __restrict__ b1,
                                       const float* __restrict__ w2,
                                       const float* __restrict__ b2) {
    if (blockIdx.x < EDGE_BLOCKS) {
        // ----- edge path: 8 edges/thread, flat -----
        const int4* src4 = (const int4*)(ei);
        const int4* dst4 = (const int4*)(ei + N_EDGES);
        int t = blockIdx.x * blockDim.x + threadIdx.x;
        int j = t * 2;
        int4 s0 = __ldcs(&src4[j]);
        int4 s1 = __ldcs(&src4[j + 1]);
        int4 d0 = __ldcs(&dst4[j]);
        int4 d1 = __ldcs(&dst4[j + 1]);
        float v0 = __ldg(&x[s0.x]);
        float v1 = __ldg(&x[s0.y]);
        float v2 = __ldg(&x[s0.z]);
        float v3 = __ldg(&x[s0.w]);
        float v4 = __ldg(&x[s1.x]);
        float v5 = __ldg(&x[s1.y]);
        float v6 = __ldg(&x[s1.z]);
        float v7 = __ldg(&x[s1.w]);
        atomicAdd(&g_agg[d0.x], v0);
        atomicAdd(&g_agg[d0.y], v1);
        atomicAdd(&g_agg[d0.z], v2);
        atomicAdd(&g_agg[d0.w], v3);
        atomicAdd(&g_agg[d1.x], v4);
        atomicAdd(&g_agg[d1.y], v5);
        atomicAdd(&g_agg[d1.z], v6);
        atomicAdd(&g_agg[d1.w], v7);
        return;
    }

    // ----- precompute path (one block of 256 threads) -----
    __shared__ float t[H];
    __shared__ int   cls[H];   // 0: w1>0, 1: w1<0, 2: w1==0 always-on, 3: off
    __shared__ int   pos[H];
    __shared__ float sw1[H], sb1[H];
    __shared__ float ssort[H];
    int tid = threadIdx.x;

    if (tid < H) {
        float w = w1[tid], b = b1[tid];
        sw1[tid] = w; sb1[tid] = b;
        if (w > 0.0f)      { cls[tid] = 0; t[tid] = -b / w; }
        else if (w < 0.0f) { cls[tid] = 1; t[tid] = -b / w; }
        else               { cls[tid] = (b > 0.0f) ? 2 : 3; t[tid] = 0.0f; }
        ssort[tid] = CUDART_INF_F;
    }
    __syncthreads();

    if (tid < H && cls[tid] < 2) {
        float tk = t[tid];
        int p = 0;
        for (int m = 0; m < H; m++) {
            if (cls[m] < 2) {
                float tm = t[m];
                if (tm < tk || (tm == tk && m < tid)) p++;
            }
        }
        pos[tid]  = p;
        ssort[p]  = tk;
    }
    __syncthreads();

    if (tid < H) g_s[tid] = ssort[tid];

    for (int e = tid; e < NREG * H; e += blockDim.x) {
        int r = e / H, j = e % H;
        float A = 0.0f;
        float B = __ldg(&b2[j]);
        for (int k = 0; k < H; k++) {
            int c = cls[k];
            bool m;
            if (c == 0)      m = (pos[k] <  r);
            else if (c == 1) m = (pos[k] >= r);
            else             m = (c == 2);
            if (m) {
                float wkj = __ldg(&w2[k * H + j]);
                A = fmaf(sw1[k], wkj, A);
                B = fmaf(sb1[k], wkj, B);
            }
        }
        g_AB[r * H + j] = make_float2(A, B);
    }
}

// ---------------------------------------------------------------------------
// 2) Per node, 4 nodes/thread (float4 I/O): h = (1+eps)*x + agg, region
//    lookup, collapsed MLP (40 FMA). Re-zeroes g_agg for the next replay.
//    sAB transposed [j][r]: conflict degree <=2.
// ---------------------------------------------------------------------------
__global__ void node_kernel(float* __restrict__ out,
                            const float* __restrict__ x,
                            const float* __restrict__ eps,
                            const float* __restrict__ w3,
                            const float* __restrict__ b3) {
    __shared__ float2 sAB[H * NREG];   // [j][r]
    for (int i = threadIdx.x; i < NREG * H; i += blockDim.x) {
        int r = i / H, j = i % H;
        sAB[j * NREG + r] = g_AB[i];
    }
    float sreg[H], w3r[H];
    #pragma unroll
    for (int m = 0; m < H; m++) {
        sreg[m] = g_s[m];
        w3r[m]  = __ldg(&w3[m]);
    }
    float bias3 = __ldg(&b3[0]);
    float e = 1.0f + __ldg(eps);
    __syncthreads();

    int i4 = blockIdx.x * blockDim.x + threadIdx.x;
    if (i4 < N_NODES / 4) {
        float4 xv = ((const float4*)x)[i4];
        float4 av = ((float4*)g_agg)[i4];
        ((float4*)g_agg)[i4] = make_float4(0.f, 0.f, 0.f, 0.f);

        float hv[4] = { fmaf(e, xv.x, av.x), fmaf(e, xv.y, av.y),
                        fmaf(e, xv.z, av.z), fmaf(e, xv.w, av.w) };
        float ov[4];
        #pragma unroll
        for (int n = 0; n < 4; n++) {
            float h = hv[n];
            int r = 0;
            #pragma unroll
            for (int m = 0; m < H; m++) r += (sreg[m] < h) ? 1 : 0;
            float acc = bias3;
            #pragma unroll
            for (int j = 0; j < H; j++) {
                float2 ab = sAB[j * NREG + r];
                float u = fmaf(ab.x, h, ab.y);
                acc = fmaf(fmaxf(u, 0.0f), w3r[j], acc);
            }
            ov[n] = acc;
        }
        ((float4*)out)[i4] = make_float4(ov[0], ov[1], ov[2], ov[3]);
    }
}

// ---------------------------------------------------------------------------
extern "C" void kernel_launch(void* const* d_in, const int* in_sizes, int n_in,
                              void* d_out, int out_size) {
    const float* x   = (const float*)d_in[0];
    const int*   ei  = (const int*)d_in[1];
    const float* eps = (const float*)d_in[2];
    const float* w1  = (const float*)d_in[3];
    const float* b1  = (const float*)d_in[4];
    const float* w2  = (const float*)d_in[5];
    const float* b2  = (const float*)d_in[6];
    const float* w3  = (const float*)d_in[7];
    const float* b3  = (const float*)d_in[8];
    float* out = (float*)d_out;

    edge_precompute_kernel<<<EDGE_BLOCKS + 1, 256>>>(ei, x, w1, b1, w2, b2);
    node_kernel<<<(N_NODES / 4 + 255) / 256, 256>>>(out, x, eps, w3, b3);
}